// round 8
// baseline (speedup 1.0000x reference)
#include <cuda_runtime.h>
#include <cuda_fp16.h>
#include <cstdint>
#include <cstddef>

// ---------------- problem constants ----------------
#define MTOK   8192            // Bt*S tokens
#define DIN    4096
#define DOUT   4096
#define NEXP   8
#define DK     32
#define RK     16
#define KLORA  (NEXP*RK)       // 128
#define KEXT   (DIN + KLORA)   // 4224
#define NROUT  (NEXP*DK*2 + KLORA)  // 640 = 256 q + 256 k + 128 h
#define SCALING 1.0f

// ---------------- device scratch (static, no allocs allowed) ----------------
__device__ __align__(1024) __half g_xh[(size_t)MTOK * KEXT];
__device__ __align__(1024) __half g_wh[(size_t)DOUT * KEXT];
__device__ __align__(1024) __half g_rh[(size_t)NROUT * DIN];
__device__ __align__(1024) float  g_P [(size_t)MTOK * NROUT];

// ---------------- small helpers ----------------
#define DEVFN __device__ __forceinline__

#define SMEM_SWZ(o) ((o) ^ (((o) >> 3) & 0x70))

DEVFN uint32_t smem_u32(const void* p) {
    uint32_t a;
    asm("{ .reg .u64 t; cvta.to.shared.u64 t, %1; cvt.u32.u64 %0, t; }"
        : "=r"(a) : "l"(p));
    return a;
}

DEVFN void cp16(uint32_t s, const void* g) {
    asm volatile("cp.async.cg.shared.global [%0], [%1], 16;" :: "r"(s), "l"(g));
}
DEVFN void cp_commit() { asm volatile("cp.async.commit_group;" ::: "memory"); }
DEVFN void cp_wait1()  { asm volatile("cp.async.wait_group 1;"  ::: "memory"); }

DEVFN void ldsm4(uint32_t* r, uint32_t a) {
    asm volatile("ldmatrix.sync.aligned.m8n8.x4.shared.b16 {%0,%1,%2,%3}, [%4];"
                 : "=r"(r[0]), "=r"(r[1]), "=r"(r[2]), "=r"(r[3]) : "r"(a));
}

DEVFN void mma16816(float* c, const uint32_t* a, const uint32_t* b) {
    asm volatile(
        "mma.sync.aligned.m16n8k16.row.col.f32.f16.f16.f32 "
        "{%0,%1,%2,%3}, {%4,%5,%6,%7}, {%8,%9}, {%0,%1,%2,%3};"
        : "+f"(c[0]), "+f"(c[1]), "+f"(c[2]), "+f"(c[3])
        : "r"(a[0]), "r"(a[1]), "r"(a[2]), "r"(a[3]), "r"(b[0]), "r"(b[1]));
}

// ---------------- conversion kernels (fp32 -> fp16) ----------------
__global__ void conv_x_kernel(const float* __restrict__ x) {
    size_t i4 = (size_t)blockIdx.x * blockDim.x + threadIdx.x;
    const size_t tot = (size_t)MTOK * DIN / 4;
    if (i4 >= tot) return;
    float4 v = ((const float4*)x)[i4];
    size_t m = i4 >> 10;              // DIN/4 = 1024 float4 per row
    size_t c = (i4 & 1023) * 4;
    size_t o = m * KEXT + c;
    __half h[4] = {__float2half(v.x), __float2half(v.y),
                   __float2half(v.z), __float2half(v.w)};
    *(uint2*)&g_xh[o] = *(uint2*)h;
}

__global__ void conv_w_kernel(const float* __restrict__ W) {
    size_t i4 = (size_t)blockIdx.x * blockDim.x + threadIdx.x;
    const size_t tot = (size_t)DOUT * DIN / 4;
    if (i4 >= tot) return;
    float4 v = ((const float4*)W)[i4];
    size_t o = i4 >> 10;              // DIN/4 = 1024 float4 per row
    size_t c = (i4 & 1023) * 4;
    size_t d = o * KEXT + c;
    __half h[4] = {__float2half(v.x), __float2half(v.y),
                   __float2half(v.z), __float2half(v.w)};
    *(uint2*)&g_wh[d] = *(uint2*)h;
}

__global__ void conv_bm_kernel(const float* __restrict__ Bm) {
    int i = blockIdx.x * blockDim.x + threadIdx.x;   // < DOUT*KLORA
    if (i >= DOUT * KLORA) return;
    int o = i >> 7;                 // output row
    int t = i & 127;                // lora col
    int e = t >> 4, r = t & 15;     // RK = 16
    float v = Bm[((size_t)e * DOUT + o) * RK + r];
    g_wh[(size_t)o * KEXT + DIN + t] = __float2half(v);
}

__global__ void conv_r_kernel(const float* __restrict__ Wq, const float* __restrict__ Wk,
                              const float* __restrict__ A) {
    int row = blockIdx.y;
    int j4 = blockIdx.x * blockDim.x + threadIdx.x;  // < 1024
    const float* src = (row < 256) ? (Wq + (size_t)row * DIN)
                    : (row < 512) ? (Wk + (size_t)(row - 256) * DIN)
                                  : (A  + (size_t)(row - 512) * DIN);
    float4 v = ((const float4*)src)[j4];
    __half h[4] = {__float2half(v.x), __float2half(v.y),
                   __float2half(v.z), __float2half(v.w)};
    *(uint2*)&g_rh[(size_t)row * DIN + j4 * 4] = *(uint2*)h;
}

// ---------------- routing softmax + hw pack ----------------
__global__ void route_kernel() {
    int wid = threadIdx.x >> 5, lane = threadIdx.x & 31;
    int m = blockIdx.x * 8 + wid;
    const float* row = g_P + (size_t)m * NROUT;
    float s[NEXP];
#pragma unroll
    for (int e = 0; e < NEXP; e++) {
        float p = row[e * 32 + lane] * row[256 + e * 32 + lane];
#pragma unroll
        for (int off = 16; off; off >>= 1) p += __shfl_xor_sync(0xffffffffu, p, off);
        s[e] = p * 0.17677669529663687f;   // 1/sqrt(32)
    }
    float mx = s[0];
#pragma unroll
    for (int e = 1; e < NEXP; e++) mx = fmaxf(mx, s[e]);
    float w[NEXP], den = 0.f;
#pragma unroll
    for (int e = 0; e < NEXP; e++) { w[e] = expf(s[e] - mx); den += w[e]; }
    float inv = SCALING / den;
#pragma unroll
    for (int t = lane; t < KLORA; t += 32) {
        int e = t >> 4;
        float hw = w[e] * inv * row[512 + t];
        g_xh[(size_t)m * KEXT + DIN + t] = __float2half(hw);
    }
}

// ---------------- fp16 mma.sync GEMM (128x128 tile, K-chunk 64, 3-stage cp.async) ----
// mode 0: routing  P[8192,640]  = x * Wr^T        (K=4096, no bias)
// mode 1: main     out[8192,4096] = [x|hw] * [W|Bm]^T + b  (K=4224)
#define STAGES      3
#define STAGE_BYTES 32768              // 2 tiles x (128 rows x 64 fp16 = 16KB)
#define SMEM_BYTES  (STAGES * STAGE_BYTES)

__global__ __launch_bounds__(256, 2) void gemm_h(int mode, float* __restrict__ outp,
                                                 const float* __restrict__ bias) {
    extern __shared__ char smem[];
    const uint32_t sb = smem_u32(smem);
    const int tid = threadIdx.x, wid = tid >> 5, lid = tid & 31;

    const __half* Bmat;
    int ldb, ldc, kchunks; float* C; bool use_bias;
    if (mode == 0) { Bmat = g_rh; ldb = DIN;  C = g_P;  ldc = NROUT; kchunks = DIN / 64;  use_bias = false; }
    else           { Bmat = g_wh; ldb = KEXT; C = outp; ldc = DOUT;  kchunks = KEXT / 64; use_bias = true;  }
    const int lda = KEXT;
    const int n0 = blockIdx.x * 128, m0 = blockIdx.y * 128;

    const char* pA = (const char*)(g_xh + (size_t)m0 * lda);
    const char* pB = (const char*)(Bmat + (size_t)n0 * ldb);
    const size_t la = (size_t)lda * 2, lb = (size_t)ldb * 2;

    // per-thread copy pattern: 8 x 16B segments per stage (2 tiles x 4)
    auto issue_stage = [&](int ck, int stage) {
        const size_t kb = (size_t)ck * 128;           // 64 fp16 = 128 bytes
        const uint32_t sbase = sb + (uint32_t)stage * STAGE_BYTES;
#pragma unroll
        for (int i = 0; i < 8; i++) {
            const int tile = i >> 2;                  // 0=A, 1=B
            int w = tid + (i & 3) * 256;              // 0..1023
            int r = w >> 3;
            int c = (w & 7) * 16;
            uint32_t so = SMEM_SWZ((uint32_t)(r * 128 + c));
            const char* g = (tile == 0 ? pA : pB) + (size_t)r * (tile == 0 ? la : lb) + kb + c;
            cp16(sbase + (uint32_t)tile * 16384u + so, g);
        }
    };

    // warp tiling: 4 warps in m (32 rows each), 2 in n (64 cols each)
    const int warp_m = wid & 3, warp_n = wid >> 2;

    float acc[2][8][4];
#pragma unroll
    for (int a = 0; a < 2; a++)
#pragma unroll
        for (int b = 0; b < 8; b++)
#pragma unroll
            for (int c = 0; c < 4; c++) acc[a][b][c] = 0.f;

    issue_stage(0, 0); cp_commit();
    issue_stage(1, 1); cp_commit();

    // ---- hoisted ldmatrix addressing ----
    // SWZ(r*128 + c) = r*128 + (c ^ ((r&7)*16)) for c < 128.
    const int a_row = warp_m * 32 + (lid & 15);           // + mi*16
    const int a_kh2 = ((lid >> 4) << 3) * 2;              // byte offset of k-half
    const int b_row = warp_n * 64 + (lid & 7);            // + nblk*8
    const int b_kh2 = ((((lid >> 3) & 1) << 3)) * 2;
    const int b_nb  = (lid >> 4);                         // nblk parity
    const uint32_t xa = (uint32_t)((a_row & 7) * 16);
    const uint32_t xb = (uint32_t)((b_row & 7) * 16);
    uint32_t aR[2], bR[4];
#pragma unroll
    for (int mi = 0; mi < 2; mi++) aR[mi] = (uint32_t)((a_row + mi * 16) * 128);
#pragma unroll
    for (int nj = 0; nj < 4; nj++) bR[nj] = (uint32_t)((b_row + (nj * 2 + b_nb) * 8) * 128);

    // double-buffered fragments (software pipeline within the K-chunk)
    uint32_t Af[2][2][4], Bf[2][8][2];

    auto load_frags = [&](uint32_t sA, uint32_t sB, int kk, int buf) {
        const uint32_t ca = (uint32_t)(kk * 2 + a_kh2) ^ xa;
        const uint32_t cb = (uint32_t)(kk * 2 + b_kh2) ^ xb;
#pragma unroll
        for (int mi = 0; mi < 2; mi++) ldsm4(Af[buf][mi], sA + aR[mi] + ca);
#pragma unroll
        for (int nj = 0; nj < 4; nj++) {
            uint32_t t[4];
            ldsm4(t, sB + bR[nj] + cb);
            Bf[buf][nj * 2][0]     = t[0]; Bf[buf][nj * 2][1]     = t[1];
            Bf[buf][nj * 2 + 1][0] = t[2]; Bf[buf][nj * 2 + 1][1] = t[3];
        }
    };

    int rstage = 0, wstage = 2;   // rotating stage indices (avoid % in loop)
    for (int ck = 0; ck < kchunks; ck++) {
        cp_wait1();
        __syncthreads();

        const uint32_t sA = sb + (uint32_t)rstage * STAGE_BYTES;
        const uint32_t sB = sA + 16384u;
        if (++rstage == STAGES) rstage = 0;

        // prime fragment pipeline for this chunk before issuing next-stage copies
        load_frags(sA, sB, 0, 0);

        if (ck + 2 < kchunks) issue_stage(ck + 2, wstage);
        cp_commit();
        if (++wstage == STAGES) wstage = 0;

#pragma unroll
        for (int i = 0; i < 4; i++) {                 // kk = i*16
            if (i < 3) load_frags(sA, sB, (i + 1) * 16, (i + 1) & 1);
            const int bsel = i & 1;
#pragma unroll
            for (int mi = 0; mi < 2; mi++)
#pragma unroll
                for (int ni = 0; ni < 8; ni++)
                    mma16816(acc[mi][ni], Af[bsel][mi], Bf[bsel][ni]);
        }
        // no trailing __syncthreads: the barrier at the top of the next
        // iteration orders all reads of stage (ck-1) before it is overwritten.
    }

    // epilogue: write 32x64 warp tile (float2 stores)
    const int gr = lid >> 2, c0 = (lid & 3) * 2;
#pragma unroll
    for (int mi = 0; mi < 2; mi++) {
        int row = m0 + warp_m * 32 + mi * 16 + gr;
#pragma unroll
        for (int ni = 0; ni < 8; ni++) {
            int col = n0 + warp_n * 64 + ni * 8 + c0;
            float b0 = use_bias ? bias[col]     : 0.f;
            float b1 = use_bias ? bias[col + 1] : 0.f;
            float2 v0 = make_float2(acc[mi][ni][0] + b0, acc[mi][ni][1] + b1);
            float2 v1 = make_float2(acc[mi][ni][2] + b0, acc[mi][ni][3] + b1);
            *(float2*)&C[(size_t)row * ldc + col]       = v0;
            *(float2*)&C[(size_t)(row + 8) * ldc + col] = v1;
        }
    }
}

// ---------------- launch ----------------
extern "C" void kernel_launch(void* const* d_in, const int* in_sizes, int n_in,
                              void* d_out, int out_size) {
    (void)in_sizes; (void)n_in; (void)out_size;
    const float* x  = (const float*)d_in[0];
    const float* W  = (const float*)d_in[1];
    const float* b  = (const float*)d_in[2];
    const float* Wq = (const float*)d_in[3];
    const float* Wk = (const float*)d_in[4];
    const float* A  = (const float*)d_in[5];
    const float* Bm = (const float*)d_in[6];
    float* out = (float*)d_out;

    cudaFuncSetAttribute(gemm_h, cudaFuncAttributeMaxDynamicSharedMemorySize, SMEM_BYTES);

    // 1. fp32 -> fp16 conversion/packing
    conv_x_kernel<<<(MTOK * (DIN / 4) + 255) / 256, 256>>>(x);
    conv_w_kernel<<<(DOUT * (DIN / 4) + 255) / 256, 256>>>(W);
    conv_bm_kernel<<<(DOUT * KLORA + 255) / 256, 256>>>(Bm);
    conv_r_kernel<<<dim3(DIN / 1024, NROUT), 256>>>(Wq, Wk, A);

    // 2. routing GEMM: P = x @ [Wq;Wk;A]^T   (8192 x 640, K=4096)
    gemm_h<<<dim3(NROUT / 128, MTOK / 128), 256, SMEM_BYTES>>>(0, nullptr, nullptr);

    // 3. softmax over experts + pack hw into extended-K columns of A
    route_kernel<<<MTOK / 8, 256>>>();

    // 4. main fused GEMM: out = [x|hw] @ [W|Bm]^T + b   (8192 x 4096, K=4224)
    gemm_h<<<dim3(DOUT / 128, MTOK / 128), 256, SMEM_BYTES>>>(1, out, b);
}

// round 9
// speedup vs baseline: 1.0788x; 1.0788x over previous
#include <cuda_runtime.h>
#include <cuda_fp16.h>
#include <cstdint>
#include <cstddef>

// ---------------- problem constants ----------------
#define MTOK   8192            // Bt*S tokens
#define DIN    4096
#define DOUT   4096
#define NEXP   8
#define DK     32
#define RK     16
#define KLORA  (NEXP*RK)       // 128
#define KEXT   (DIN + KLORA)   // 4224
#define NROUT  (NEXP*DK*2 + KLORA)  // 640 = 256 q + 256 k + 128 h
#define SCALING 1.0f

// ---------------- device scratch (static, no allocs allowed) ----------------
__device__ __align__(1024) __half g_xh[(size_t)MTOK * KEXT];
__device__ __align__(1024) __half g_wh[(size_t)DOUT * KEXT];
__device__ __align__(1024) __half g_rh[(size_t)NROUT * DIN];
__device__ __align__(1024) float  g_P [(size_t)MTOK * NROUT];

// ---------------- small helpers ----------------
#define DEVFN __device__ __forceinline__

#define SMEM_SWZ(o) ((o) ^ (((o) >> 3) & 0x70))

DEVFN uint32_t smem_u32(const void* p) {
    uint32_t a;
    asm("{ .reg .u64 t; cvta.to.shared.u64 t, %1; cvt.u32.u64 %0, t; }"
        : "=r"(a) : "l"(p));
    return a;
}

DEVFN void cp16(uint32_t s, const void* g) {
    asm volatile("cp.async.cg.shared.global [%0], [%1], 16;" :: "r"(s), "l"(g));
}
DEVFN void cp_commit() { asm volatile("cp.async.commit_group;" ::: "memory"); }
DEVFN void cp_wait1()  { asm volatile("cp.async.wait_group 1;"  ::: "memory"); }

DEVFN void ldsm4(uint32_t* r, uint32_t a) {
    asm volatile("ldmatrix.sync.aligned.m8n8.x4.shared.b16 {%0,%1,%2,%3}, [%4];"
                 : "=r"(r[0]), "=r"(r[1]), "=r"(r[2]), "=r"(r[3]) : "r"(a));
}

DEVFN void mma16816(float* c, const uint32_t* a, const uint32_t* b) {
    asm volatile(
        "mma.sync.aligned.m16n8k16.row.col.f32.f16.f16.f32 "
        "{%0,%1,%2,%3}, {%4,%5,%6,%7}, {%8,%9}, {%0,%1,%2,%3};"
        : "+f"(c[0]), "+f"(c[1]), "+f"(c[2]), "+f"(c[3])
        : "r"(a[0]), "r"(a[1]), "r"(a[2]), "r"(a[3]), "r"(b[0]), "r"(b[1]));
}

// ---------------- conversion kernels (fp32 -> fp16, 8 elems/thread) ----------------
__global__ void conv_x_kernel(const float* __restrict__ x) {
    size_t i8 = (size_t)blockIdx.x * blockDim.x + threadIdx.x;
    const size_t tot = (size_t)MTOK * DIN / 8;
    if (i8 >= tot) return;
    const float4* src = (const float4*)x + i8 * 2;
    float4 v0 = src[0], v1 = src[1];
    size_t m = i8 >> 9;               // DIN/8 = 512 groups per row
    size_t c = (i8 & 511) * 8;
    __half h[8] = {__float2half(v0.x), __float2half(v0.y), __float2half(v0.z), __float2half(v0.w),
                   __float2half(v1.x), __float2half(v1.y), __float2half(v1.z), __float2half(v1.w)};
    *(uint4*)&g_xh[m * KEXT + c] = *(uint4*)h;
}

__global__ void conv_w_kernel(const float* __restrict__ W) {
    size_t i8 = (size_t)blockIdx.x * blockDim.x + threadIdx.x;
    const size_t tot = (size_t)DOUT * DIN / 8;
    if (i8 >= tot) return;
    const float4* src = (const float4*)W + i8 * 2;
    float4 v0 = src[0], v1 = src[1];
    size_t o = i8 >> 9;
    size_t c = (i8 & 511) * 8;
    __half h[8] = {__float2half(v0.x), __float2half(v0.y), __float2half(v0.z), __float2half(v0.w),
                   __float2half(v1.x), __float2half(v1.y), __float2half(v1.z), __float2half(v1.w)};
    *(uint4*)&g_wh[o * KEXT + c] = *(uint4*)h;
}

__global__ void conv_bm_kernel(const float* __restrict__ Bm) {
    int i = blockIdx.x * blockDim.x + threadIdx.x;   // < DOUT*KLORA
    if (i >= DOUT * KLORA) return;
    int o = i >> 7;                 // output row
    int t = i & 127;                // lora col
    int e = t >> 4, r = t & 15;     // RK = 16
    float v = Bm[((size_t)e * DOUT + o) * RK + r];
    g_wh[(size_t)o * KEXT + DIN + t] = __float2half(v);
}

__global__ void conv_r_kernel(const float* __restrict__ Wq, const float* __restrict__ Wk,
                              const float* __restrict__ A) {
    int row = blockIdx.y;
    int j8 = blockIdx.x * blockDim.x + threadIdx.x;  // < 512
    const float* src = (row < 256) ? (Wq + (size_t)row * DIN)
                    : (row < 512) ? (Wk + (size_t)(row - 256) * DIN)
                                  : (A  + (size_t)(row - 512) * DIN);
    const float4* s4 = (const float4*)src + j8 * 2;
    float4 v0 = s4[0], v1 = s4[1];
    __half h[8] = {__float2half(v0.x), __float2half(v0.y), __float2half(v0.z), __float2half(v0.w),
                   __float2half(v1.x), __float2half(v1.y), __float2half(v1.z), __float2half(v1.w)};
    *(uint4*)&g_rh[(size_t)row * DIN + j8 * 8] = *(uint4*)h;
}

// ---------------- routing softmax + hw pack ----------------
__global__ void route_kernel() {
    int wid = threadIdx.x >> 5, lane = threadIdx.x & 31;
    int m = blockIdx.x * 8 + wid;
    const float* row = g_P + (size_t)m * NROUT;
    float s[NEXP];
#pragma unroll
    for (int e = 0; e < NEXP; e++) {
        float p = row[e * 32 + lane] * row[256 + e * 32 + lane];
#pragma unroll
        for (int off = 16; off; off >>= 1) p += __shfl_xor_sync(0xffffffffu, p, off);
        s[e] = p * 0.17677669529663687f;   // 1/sqrt(32)
    }
    float mx = s[0];
#pragma unroll
    for (int e = 1; e < NEXP; e++) mx = fmaxf(mx, s[e]);
    float w[NEXP], den = 0.f;
#pragma unroll
    for (int e = 0; e < NEXP; e++) { w[e] = expf(s[e] - mx); den += w[e]; }
    float inv = SCALING / den;
#pragma unroll
    for (int t = lane; t < KLORA; t += 32) {
        int e = t >> 4;
        float hw = w[e] * inv * row[512 + t];
        g_xh[(size_t)m * KEXT + DIN + t] = __float2half(hw);
    }
}

// ---------------- fp16 mma.sync GEMM, templated tile (BMxBN=128, K-chunk 64) ----
// BM: CTA tile rows. WMW: warps along m (warp m-tile = BM/WMW = 32 always).
// 256 threads, 3-stage cp.async pipeline. R7-style mainloop (ptxas schedules).
#define STAGES 3

template<int BM, int WMW>
__global__ __launch_bounds__(256, 2) void gemm_t(
        const __half* __restrict__ Amat, const __half* __restrict__ Bmat,
        int lda, int ldb, int ldc, int kchunks,
        float* __restrict__ C, const float* __restrict__ bias) {
    constexpr int WNW = 8 / WMW;             // warps along n
    constexpr int WN  = 128 / WNW;           // warp n-tile
    constexpr int NI  = WN / 8;              // n8 blocks per warp
    constexpr int STAGE_BYTES = (BM + 128) * 128;

    extern __shared__ char smem[];
    const uint32_t sb = smem_u32(smem);
    const int tid = threadIdx.x, wid = tid >> 5, lid = tid & 31;

    const int n0 = blockIdx.x * 128, m0 = blockIdx.y * BM;

    const char* pA = (const char*)(Amat + (size_t)m0 * lda);
    const char* pB = (const char*)(Bmat + (size_t)n0 * ldb);
    const size_t la = (size_t)lda * 2, lb = (size_t)ldb * 2;

    auto issue_stage = [&](int ck, int stage) {
        const size_t kb = (size_t)ck * 128;           // 64 fp16 = 128 bytes
        const uint32_t sbase = sb + (uint32_t)stage * STAGE_BYTES;
#pragma unroll
        for (int i = 0; i < BM * 8 / 256; i++) {      // A rows
            int s = tid + i * 256;
            int r = s >> 3, c = (s & 7) * 16;
            uint32_t so = SMEM_SWZ((uint32_t)(r * 128 + c));
            cp16(sbase + so, pA + (size_t)r * la + kb + c);
        }
#pragma unroll
        for (int i = 0; i < 4; i++) {                 // B rows (128)
            int s = tid + i * 256;
            int r = s >> 3, c = (s & 7) * 16;
            uint32_t so = SMEM_SWZ((uint32_t)(r * 128 + c));
            cp16(sbase + (uint32_t)(BM * 128) + so, pB + (size_t)r * lb + kb + c);
        }
    };

    const int warp_m = wid & (WMW - 1), warp_n = wid / WMW;

    float acc[2][NI][4];
#pragma unroll
    for (int a = 0; a < 2; a++)
#pragma unroll
        for (int b = 0; b < NI; b++)
#pragma unroll
            for (int c = 0; c < 4; c++) acc[a][b][c] = 0.f;

    issue_stage(0, 0); cp_commit();
    issue_stage(1, 1); cp_commit();

    // hoisted ldmatrix addressing: SWZ(r*128+c) = r*128 + (c ^ ((r&7)*16))
    const int a_row = warp_m * 32 + (lid & 15);
    const int a_kh2 = ((lid >> 4) << 3) * 2;
    const int b_row = warp_n * WN + (lid & 7);
    const int b_kh2 = ((((lid >> 3) & 1) << 3)) * 2;
    const int b_nb  = (lid >> 4);
    const uint32_t xa = (uint32_t)((a_row & 7) * 16);
    const uint32_t xb = (uint32_t)((b_row & 7) * 16);
    uint32_t aR[2], bR[NI / 2];
#pragma unroll
    for (int mi = 0; mi < 2; mi++) aR[mi] = (uint32_t)((a_row + mi * 16) * 128);
#pragma unroll
    for (int nj = 0; nj < NI / 2; nj++)
        bR[nj] = (uint32_t)((b_row + (nj * 2 + b_nb) * 8) * 128);

    int rstage = 0, wstage = 2;
    for (int ck = 0; ck < kchunks; ck++) {
        cp_wait1();
        __syncthreads();
        if (ck + 2 < kchunks) issue_stage(ck + 2, wstage);
        cp_commit();
        if (++wstage == STAGES) wstage = 0;

        const uint32_t sA = sb + (uint32_t)rstage * STAGE_BYTES;
        const uint32_t sB = sA + (uint32_t)(BM * 128);
        if (++rstage == STAGES) rstage = 0;

#pragma unroll
        for (int kk = 0; kk < 64; kk += 16) {
            const uint32_t ca = (uint32_t)(kk * 2 + a_kh2) ^ xa;
            const uint32_t cb = (uint32_t)(kk * 2 + b_kh2) ^ xb;
            uint32_t Af[2][4], Bf[NI][2];
#pragma unroll
            for (int mi = 0; mi < 2; mi++) ldsm4(Af[mi], sA + aR[mi] + ca);
#pragma unroll
            for (int nj = 0; nj < NI / 2; nj++) {
                uint32_t t[4];
                ldsm4(t, sB + bR[nj] + cb);
                Bf[nj * 2][0]     = t[0]; Bf[nj * 2][1]     = t[1];
                Bf[nj * 2 + 1][0] = t[2]; Bf[nj * 2 + 1][1] = t[3];
            }
#pragma unroll
            for (int mi = 0; mi < 2; mi++)
#pragma unroll
                for (int ni = 0; ni < NI; ni++) mma16816(acc[mi][ni], Af[mi], Bf[ni]);
        }
        // no trailing __syncthreads: next iteration's barrier orders stage reuse.
    }

    // epilogue: write 32xWN warp tile (float2 stores)
    const int gr = lid >> 2, c0 = (lid & 3) * 2;
    const bool use_bias = (bias != nullptr);
#pragma unroll
    for (int mi = 0; mi < 2; mi++) {
        int row = m0 + warp_m * 32 + mi * 16 + gr;
#pragma unroll
        for (int ni = 0; ni < NI; ni++) {
            int col = n0 + warp_n * WN + ni * 8 + c0;
            float b0 = use_bias ? bias[col]     : 0.f;
            float b1 = use_bias ? bias[col + 1] : 0.f;
            float2 v0 = make_float2(acc[mi][ni][0] + b0, acc[mi][ni][1] + b1);
            float2 v1 = make_float2(acc[mi][ni][2] + b0, acc[mi][ni][3] + b1);
            *(float2*)&C[(size_t)row * ldc + col]       = v0;
            *(float2*)&C[(size_t)(row + 8) * ldc + col] = v1;
        }
    }
}

// ---------------- launch ----------------
extern "C" void kernel_launch(void* const* d_in, const int* in_sizes, int n_in,
                              void* d_out, int out_size) {
    (void)in_sizes; (void)n_in; (void)out_size;
    const float* x  = (const float*)d_in[0];
    const float* W  = (const float*)d_in[1];
    const float* b  = (const float*)d_in[2];
    const float* Wq = (const float*)d_in[3];
    const float* Wk = (const float*)d_in[4];
    const float* A  = (const float*)d_in[5];
    const float* Bm = (const float*)d_in[6];
    float* out = (float*)d_out;

    __half* xh = nullptr; __half* wh = nullptr; __half* rh = nullptr; float* P = nullptr;
    cudaGetSymbolAddress((void**)&xh, g_xh);
    cudaGetSymbolAddress((void**)&wh, g_wh);
    cudaGetSymbolAddress((void**)&rh, g_rh);
    cudaGetSymbolAddress((void**)&P,  g_P);

    constexpr int SMEM_MAIN  = STAGES * (128 + 128) * 128;  // 96 KB
    constexpr int SMEM_ROUTE = STAGES * (64 + 128) * 128;   // 72 KB
    cudaFuncSetAttribute(gemm_t<128, 4>, cudaFuncAttributeMaxDynamicSharedMemorySize, SMEM_MAIN);
    cudaFuncSetAttribute(gemm_t<64, 2>,  cudaFuncAttributeMaxDynamicSharedMemorySize, SMEM_ROUTE);

    // 1. fp32 -> fp16 conversion/packing
    conv_x_kernel<<<(MTOK * (DIN / 8) + 255) / 256, 256>>>(x);
    conv_w_kernel<<<(DOUT * (DIN / 8) + 255) / 256, 256>>>(W);
    conv_bm_kernel<<<(DOUT * KLORA + 255) / 256, 256>>>(Bm);
    conv_r_kernel<<<dim3(DIN / 2048, NROUT), 256>>>(Wq, Wk, A);

    // 2. routing GEMM: P = x @ [Wq;Wk;A]^T   (8192 x 640, K=4096), BM=64 tiles
    gemm_t<64, 2><<<dim3(NROUT / 128, MTOK / 64), 256, SMEM_ROUTE>>>(
        xh, rh, KEXT, DIN, NROUT, DIN / 64, P, nullptr);

    // 3. softmax over experts + pack hw into extended-K columns of A
    route_kernel<<<MTOK / 8, 256>>>();

    // 4. main fused GEMM: out = [x|hw] @ [W|Bm]^T + b   (8192 x 4096, K=4224)
    gemm_t<128, 4><<<dim3(DOUT / 128, MTOK / 128), 256, SMEM_MAIN>>>(
        xh, wh, KEXT, KEXT, DOUT, KEXT / 64, out, b);
}

// round 11
// speedup vs baseline: 1.1023x; 1.0218x over previous
#include <cuda_runtime.h>
#include <cuda_fp16.h>
#include <cstdint>
#include <cstddef>

// ---------------- problem constants ----------------
#define MTOK   8192            // Bt*S tokens
#define DIN    4096
#define DOUT   4096
#define NEXP   8
#define DK     32
#define RK     16
#define KLORA  (NEXP*RK)       // 128
#define KEXT   (DIN + KLORA)   // 4224
#define NROUT  (NEXP*DK*2 + KLORA)  // 640 = 256 q + 256 k + 128 h
#define SCALING 1.0f

// ---------------- device scratch (static, no allocs allowed) ----------------
__device__ __align__(1024) __half g_xh[(size_t)MTOK * KEXT];
__device__ __align__(1024) __half g_wh[(size_t)DOUT * KEXT];
__device__ __align__(1024) __half g_rh[(size_t)NROUT * DIN];
__device__ __align__(1024) float  g_P [(size_t)MTOK * NROUT];   // split-K half 0
__device__ __align__(1024) float  g_P2[(size_t)MTOK * NROUT];   // split-K half 1

// ---------------- small helpers ----------------
#define DEVFN __device__ __forceinline__

#define SMEM_SWZ(o) ((o) ^ (((o) >> 3) & 0x70))

DEVFN uint32_t smem_u32(const void* p) {
    uint32_t a;
    asm("{ .reg .u64 t; cvta.to.shared.u64 t, %1; cvt.u32.u64 %0, t; }"
        : "=r"(a) : "l"(p));
    return a;
}

DEVFN void cp16(uint32_t s, const void* g) {
    asm volatile("cp.async.cg.shared.global [%0], [%1], 16;" :: "r"(s), "l"(g));
}
DEVFN void cp_commit() { asm volatile("cp.async.commit_group;" ::: "memory"); }
DEVFN void cp_wait1()  { asm volatile("cp.async.wait_group 1;"  ::: "memory"); }

DEVFN void ldsm4(uint32_t* r, uint32_t a) {
    asm volatile("ldmatrix.sync.aligned.m8n8.x4.shared.b16 {%0,%1,%2,%3}, [%4];"
                 : "=r"(r[0]), "=r"(r[1]), "=r"(r[2]), "=r"(r[3]) : "r"(a));
}

DEVFN void mma16816(float* c, const uint32_t* a, const uint32_t* b) {
    asm volatile(
        "mma.sync.aligned.m16n8k16.row.col.f32.f16.f16.f32 "
        "{%0,%1,%2,%3}, {%4,%5,%6,%7}, {%8,%9}, {%0,%1,%2,%3};"
        : "+f"(c[0]), "+f"(c[1]), "+f"(c[2]), "+f"(c[3])
        : "r"(a[0]), "r"(a[1]), "r"(a[2]), "r"(a[3]), "r"(b[0]), "r"(b[1]));
}

DEVFN void cvt8_store(void* dst, float4 v0, float4 v1) {
    __half2 h[4];
    h[0] = __float22half2_rn(make_float2(v0.x, v0.y));
    h[1] = __float22half2_rn(make_float2(v0.z, v0.w));
    h[2] = __float22half2_rn(make_float2(v1.x, v1.y));
    h[3] = __float22half2_rn(make_float2(v1.z, v1.w));
    *(uint4*)dst = *(uint4*)h;
}

// ---------------- merged conversion kernel (fp32 -> fp16, 8 elems/thread) -------
// Region granule counts (8-elem granules), all exact multiples of 256:
#define NG_X  ((size_t)MTOK * DIN / 8)     // 4194304
#define NG_W  ((size_t)DOUT * DIN / 8)     // 2097152
#define NG_R  ((size_t)NROUT * DIN / 8)    // 327680
#define NG_BM ((size_t)DOUT * KLORA / 8)   // 65536
#define CONV_BLOCKS ((NG_X + NG_W + NG_R + NG_BM) / 256)

__global__ void conv_all(const float* __restrict__ x, const float* __restrict__ W,
                         const float* __restrict__ Bm, const float* __restrict__ Wq,
                         const float* __restrict__ Wk, const float* __restrict__ A) {
    size_t gi = (size_t)blockIdx.x * 256 + threadIdx.x;
    if (gi < NG_X) {
        const float4* s = (const float4*)x + gi * 2;
        float4 v0 = s[0], v1 = s[1];
        size_t m = gi >> 9, c = (gi & 511) * 8;        // DIN/8 = 512
        cvt8_store(&g_xh[m * KEXT + c], v0, v1);
        return;
    }
    gi -= NG_X;
    if (gi < NG_W) {
        const float4* s = (const float4*)W + gi * 2;
        float4 v0 = s[0], v1 = s[1];
        size_t o = gi >> 9, c = (gi & 511) * 8;
        cvt8_store(&g_wh[o * KEXT + c], v0, v1);
        return;
    }
    gi -= NG_W;
    if (gi < NG_R) {
        size_t row = gi >> 9, c = (gi & 511) * 8;
        const float* src = (row < 256) ? (Wq + row * DIN)
                        : (row < 512) ? (Wk + (row - 256) * DIN)
                                      : (A  + (row - 512) * DIN);
        const float4* s = (const float4*)(src + c);
        cvt8_store(&g_rh[row * DIN + c], s[0], s[1]);
        return;
    }
    gi -= NG_R;
    {
        // Bm gather: 16 granules per output row o; t0 = 0,8,...,120
        size_t o = gi >> 4;
        int t0 = (int)(gi & 15) * 8;
        int e = t0 >> 4, r0 = t0 & 15;                 // r0 in {0,8}, 8 contiguous r
        const float4* s = (const float4*)(Bm + ((size_t)e * DOUT + o) * RK + r0);
        cvt8_store(&g_wh[o * KEXT + DIN + t0], s[0], s[1]);
    }
}

// ---------------- routing softmax + hw pack (sums split-K halves) ----------------
__global__ void route_kernel() {
    int wid = threadIdx.x >> 5, lane = threadIdx.x & 31;
    int m = blockIdx.x * 8 + wid;
    const float* r0 = g_P  + (size_t)m * NROUT;
    const float* r1 = g_P2 + (size_t)m * NROUT;
    float s[NEXP];
#pragma unroll
    for (int e = 0; e < NEXP; e++) {
        int iq = e * 32 + lane, ik = 256 + e * 32 + lane;
        float q = r0[iq] + r1[iq];
        float k = r0[ik] + r1[ik];
        float p = q * k;
#pragma unroll
        for (int off = 16; off; off >>= 1) p += __shfl_xor_sync(0xffffffffu, p, off);
        s[e] = p * 0.17677669529663687f;   // 1/sqrt(32)
    }
    float mx = s[0];
#pragma unroll
    for (int e = 1; e < NEXP; e++) mx = fmaxf(mx, s[e]);
    float w[NEXP], den = 0.f;
#pragma unroll
    for (int e = 0; e < NEXP; e++) { w[e] = expf(s[e] - mx); den += w[e]; }
    float inv = SCALING / den;
#pragma unroll
    for (int t = lane; t < KLORA; t += 32) {
        int e = t >> 4;
        float h = r0[512 + t] + r1[512 + t];
        float hw = w[e] * inv * h;
        g_xh[(size_t)m * KEXT + DIN + t] = __float2half(hw);
    }
}

// ---------------- fp16 mma.sync GEMM, templated tile (BMxBN=128, K-chunk 64) ----
// BM: CTA tile rows. WMW: warps along m (warp m-tile = BM/WMW = 32 always).
// 256 threads, 3-stage cp.async pipeline. blockIdx.z = split-K slice.
#define STAGES 3

template<int BM, int WMW>
__global__ __launch_bounds__(256, 2) void gemm_t(
        const __half* __restrict__ Amat, const __half* __restrict__ Bmat,
        int lda, int ldb, int ldc, int kchunks,
        float* __restrict__ C, const float* __restrict__ bias,
        size_t csplit) {
    constexpr int WNW = 8 / WMW;             // warps along n
    constexpr int WN  = 128 / WNW;           // warp n-tile
    constexpr int NI  = WN / 8;              // n8 blocks per warp
    constexpr int STAGE_BYTES = (BM + 128) * 128;

    extern __shared__ char smem[];
    const uint32_t sb = smem_u32(smem);
    const int tid = threadIdx.x, wid = tid >> 5, lid = tid & 31;

    const int n0 = blockIdx.x * 128, m0 = blockIdx.y * BM;
    const size_t koff = (size_t)blockIdx.z * kchunks * 64;
    C += (size_t)blockIdx.z * csplit;

    const char* pA = (const char*)(Amat + (size_t)m0 * lda + koff);
    const char* pB = (const char*)(Bmat + (size_t)n0 * ldb + koff);
    const size_t la = (size_t)lda * 2, lb = (size_t)ldb * 2;

    auto issue_stage = [&](int ck, int stage) {
        const size_t kb = (size_t)ck * 128;           // 64 fp16 = 128 bytes
        const uint32_t sbase = sb + (uint32_t)stage * STAGE_BYTES;
#pragma unroll
        for (int i = 0; i < BM * 8 / 256; i++) {      // A rows
            int s = tid + i * 256;
            int r = s >> 3, c = (s & 7) * 16;
            uint32_t so = SMEM_SWZ((uint32_t)(r * 128 + c));
            cp16(sbase + so, pA + (size_t)r * la + kb + c);
        }
#pragma unroll
        for (int i = 0; i < 4; i++) {                 // B rows (128)
            int s = tid + i * 256;
            int r = s >> 3, c = (s & 7) * 16;
            uint32_t so = SMEM_SWZ((uint32_t)(r * 128 + c));
            cp16(sbase + (uint32_t)(BM * 128) + so, pB + (size_t)r * lb + kb + c);
        }
    };

    const int warp_m = wid & (WMW - 1), warp_n = wid / WMW;

    float acc[2][NI][4];
#pragma unroll
    for (int a = 0; a < 2; a++)
#pragma unroll
        for (int b = 0; b < NI; b++)
#pragma unroll
            for (int c = 0; c < 4; c++) acc[a][b][c] = 0.f;

    issue_stage(0, 0); cp_commit();
    issue_stage(1, 1); cp_commit();

    // hoisted ldmatrix addressing: SWZ(r*128+c) = r*128 + (c ^ ((r&7)*16))
    const int a_row = warp_m * 32 + (lid & 15);
    const int a_kh2 = ((lid >> 4) << 3) * 2;
    const int b_row = warp_n * WN + (lid & 7);
    const int b_kh2 = ((((lid >> 3) & 1) << 3)) * 2;
    const int b_nb  = (lid >> 4);
    const uint32_t xa = (uint32_t)((a_row & 7) * 16);
    const uint32_t xb = (uint32_t)((b_row & 7) * 16);
    uint32_t aR[2], bR[NI / 2];
#pragma unroll
    for (int mi = 0; mi < 2; mi++) aR[mi] = (uint32_t)((a_row + mi * 16) * 128);
#pragma unroll
    for (int nj = 0; nj < NI / 2; nj++)
        bR[nj] = (uint32_t)((b_row + (nj * 2 + b_nb) * 8) * 128);

    int rstage = 0, wstage = 2;
    for (int ck = 0; ck < kchunks; ck++) {
        cp_wait1();
        __syncthreads();
        if (ck + 2 < kchunks) issue_stage(ck + 2, wstage);
        cp_commit();
        if (++wstage == STAGES) wstage = 0;

        const uint32_t sA = sb + (uint32_t)rstage * STAGE_BYTES;
        const uint32_t sB = sA + (uint32_t)(BM * 128);
        if (++rstage == STAGES) rstage = 0;

#pragma unroll
        for (int kk = 0; kk < 64; kk += 16) {
            const uint32_t ca = (uint32_t)(kk * 2 + a_kh2) ^ xa;
            const uint32_t cb = (uint32_t)(kk * 2 + b_kh2) ^ xb;
            uint32_t Af[2][4], Bf[NI][2];
#pragma unroll
            for (int mi = 0; mi < 2; mi++) ldsm4(Af[mi], sA + aR[mi] + ca);
#pragma unroll
            for (int nj = 0; nj < NI / 2; nj++) {
                uint32_t t[4];
                ldsm4(t, sB + bR[nj] + cb);
                Bf[nj * 2][0]     = t[0]; Bf[nj * 2][1]     = t[1];
                Bf[nj * 2 + 1][0] = t[2]; Bf[nj * 2 + 1][1] = t[3];
            }
#pragma unroll
            for (int mi = 0; mi < 2; mi++)
#pragma unroll
                for (int ni = 0; ni < NI; ni++) mma16816(acc[mi][ni], Af[mi], Bf[ni]);
        }
        // no trailing __syncthreads: next iteration's barrier orders stage reuse.
    }

    // epilogue: write 32xWN warp tile (float2 stores)
    const int gr = lid >> 2, c0 = (lid & 3) * 2;
    const bool use_bias = (bias != nullptr);
#pragma unroll
    for (int mi = 0; mi < 2; mi++) {
        int row = m0 + warp_m * 32 + mi * 16 + gr;
#pragma unroll
        for (int ni = 0; ni < NI; ni++) {
            int col = n0 + warp_n * WN + ni * 8 + c0;
            float b0 = use_bias ? bias[col]     : 0.f;
            float b1 = use_bias ? bias[col + 1] : 0.f;
            float2 v0 = make_float2(acc[mi][ni][0] + b0, acc[mi][ni][1] + b1);
            float2 v1 = make_float2(acc[mi][ni][2] + b0, acc[mi][ni][3] + b1);
            *(float2*)&C[(size_t)row * ldc + col]       = v0;
            *(float2*)&C[(size_t)(row + 8) * ldc + col] = v1;
        }
    }
}

// ---------------- launch ----------------
extern "C" void kernel_launch(void* const* d_in, const int* in_sizes, int n_in,
                              void* d_out, int out_size) {
    (void)in_sizes; (void)n_in; (void)out_size;
    const float* x  = (const float*)d_in[0];
    const float* W  = (const float*)d_in[1];
    const float* b  = (const float*)d_in[2];
    const float* Wq = (const float*)d_in[3];
    const float* Wk = (const float*)d_in[4];
    const float* A  = (const float*)d_in[5];
    const float* Bm = (const float*)d_in[6];
    float* out = (float*)d_out;

    __half* xh = nullptr; __half* wh = nullptr; __half* rh = nullptr; float* P = nullptr;
    cudaGetSymbolAddress((void**)&xh, g_xh);
    cudaGetSymbolAddress((void**)&wh, g_wh);
    cudaGetSymbolAddress((void**)&rh, g_rh);
    cudaGetSymbolAddress((void**)&P,  g_P);

    constexpr int SMEM_MAIN  = STAGES * (128 + 128) * 128;  // 96 KB
    constexpr int SMEM_ROUTE = STAGES * (64 + 128) * 128;   // 72 KB
    cudaFuncSetAttribute(gemm_t<128, 4>, cudaFuncAttributeMaxDynamicSharedMemorySize, SMEM_MAIN);
    cudaFuncSetAttribute(gemm_t<64, 2>,  cudaFuncAttributeMaxDynamicSharedMemorySize, SMEM_ROUTE);

    // 1. fp32 -> fp16 conversion/packing (single merged kernel)
    conv_all<<<(unsigned)CONV_BLOCKS, 256>>>(x, W, Bm, Wq, Wk, A);

    // 2. routing GEMM, split-K=2: P[z] = x @ [Wq;Wk;A]^T over K half z
    gemm_t<64, 2><<<dim3(NROUT / 128, MTOK / 64, 2), 256, SMEM_ROUTE>>>(
        xh, rh, KEXT, DIN, NROUT, DIN / 128, P, nullptr, (size_t)MTOK * NROUT);

    // 3. softmax over experts (sums split halves) + pack hw into extended-K cols
    route_kernel<<<MTOK / 8, 256>>>();

    // 4. main fused GEMM: out = [x|hw] @ [W|Bm]^T + b   (8192 x 4096, K=4224)
    gemm_t<128, 4><<<dim3(DOUT / 128, MTOK / 128, 1), 256, SMEM_MAIN>>>(
        xh, wh, KEXT, KEXT, DOUT, KEXT / 64, out, b, 0);
}